// round 17
// baseline (speedup 1.0000x reference)
#include <cuda_runtime.h>
#include <cuda_fp16.h>
#include <cstdint>

#define N_NODES 50000
#define N_EDGES 600000
#define IN_DIM  64
#define HIDDEN  128
#define N_REL   10
#define N_LAYERS 6
#define N_GRAPHS 64
#define LN_EPS  1e-5f

#define NRN     (N_REL * N_NODES)          // 500000 (rel,src) slots
#define ROOTPAD 50048                      // pad128(50000)
#define NJMAX   (ROOTPAD * 11)             // worst-case padded job rows = 550528
#define MAXTILES (NJMAX / 128)             // 4301

#define SCAN_BLK  256
#define SCAN_GRID ((NRN + SCAN_BLK - 1) / SCAN_BLK)   // 1954

// ---------------- device scratch ----------------
__device__ uint32_t g_Yc[(size_t)NJMAX * 64];      // compact Y, fp16x2 per u32 (<=141MB)
__device__ float g_h[2][(size_t)N_NODES * HIDDEN]; // ping-pong features (fp32)
__device__ __half g_hh[(size_t)N_NODES * HIDDEN];  // fp16 copy of current h (GEMM A side)
__device__ __half g_Bwh[(size_t)N_LAYERS * 11 * 128 * 128]; // fp16 weights [l][rr][n][k] (transposed)
__device__ int   g_cnt[N_NODES * N_REL];           // in-degree per (dst,rel)
__device__ int   g_cntSR[NRN];                     // out-degree per (rel,src)
__device__ int   g_cntd[N_NODES];                  // per-dst in-degree (derived in scan_dst)
__device__ int   g_start[N_NODES];                 // CSR offsets (by dst)
__device__ int   g_fill[N_NODES];                  // CSR fill cursors
__device__ int   g_jobrank[NRN];
__device__ int   g_cumRel[N_REL + 1];
__device__ int   g_jb[12];
__device__ int   g_joblist[NJMAX];
__device__ int   g_jobidx[NRN];
__device__ int2  g_epk[N_EDGES];                   // per-edge packed {coff, cw bits}
__device__ int   g_blkcnt[SCAN_GRID];
__device__ int   g_blkbase[SCAN_GRID];
__device__ int   g_done;                           // last-block flag for fused jb

__device__ __forceinline__ uint32_t pack_h2(float lo, float hi) {
    __half2 h = __floats2half2_rn(lo, hi);
    return *(uint32_t*)&h;
}

__device__ __forceinline__ uint32_t smem_u32(const void* p) {
    uint32_t a;
    asm("{ .reg .u64 t; cvta.to.shared.u64 t, %1; cvt.u32.u64 %0, t; }" : "=r"(a) : "l"(p));
    return a;
}

__device__ __forceinline__ void mma_f16(float* c, const uint32_t* a, const uint32_t* b) {
    asm volatile(
        "mma.sync.aligned.m16n8k16.row.col.f32.f16.f16.f32 "
        "{%0,%1,%2,%3}, {%4,%5,%6,%7}, {%8,%9}, {%0,%1,%2,%3};"
        : "+f"(c[0]), "+f"(c[1]), "+f"(c[2]), "+f"(c[3])
        : "r"(a[0]), "r"(a[1]), "r"(a[2]), "r"(a[3]), "r"(b[0]), "r"(b[1]));
}

#define LDM_X4(r0, r1, r2, r3, addr) \
    asm volatile("ldmatrix.sync.aligned.m8n8.x4.shared.b16 {%0,%1,%2,%3}, [%4];" \
                 : "=r"(r0), "=r"(r1), "=r"(r2), "=r"(r3) : "r"(addr))

// ---------------- setup kernels (once per call) ----------------
__global__ void init_kernel() {
    int i = blockIdx.x * blockDim.x + threadIdx.x;
    if (i < NRN) { g_cntSR[i] = 0; }
    if (i < N_NODES * N_REL) g_cnt[i] = 0;
    if (i < N_NODES) g_fill[i] = 0;
    if (i == 0) g_done = 0;
}

__global__ void count_kernel(const int* __restrict__ ei, const int* __restrict__ et) {
    int e = blockIdx.x * blockDim.x + threadIdx.x;
    if (e >= N_EDGES) return;
    int src = ei[e];
    int dst = ei[N_EDGES + e];
    int r = et[e];
    atomicAdd(&g_cnt[dst * N_REL + r], 1);
    atomicAdd(&g_cntSR[r * N_NODES + src], 1);
}

// derive g_cntd from g_cnt; exclusive scan -> g_start (single block)
__global__ void scan_dst_kernel() {
    __shared__ int part[1024];
    int t = threadIdx.x;
    const int CH = (N_NODES + 1023) / 1024;
    int base = t * CH;
    int s = 0;
    for (int i = 0; i < CH; i++) {
        int idx = base + i;
        if (idx < N_NODES) {
            int cd = 0;
            #pragma unroll
            for (int r = 0; r < N_REL; r++) cd += g_cnt[idx * N_REL + r];
            g_cntd[idx] = cd;
            s += cd;
        }
    }
    part[t] = s;
    __syncthreads();
    for (int off = 1; off < 1024; off <<= 1) {
        int v = (t >= off) ? part[t - off] : 0;
        __syncthreads();
        part[t] += v;
        __syncthreads();
    }
    int run = (t > 0) ? part[t - 1] : 0;
    for (int i = 0; i < CH; i++) {
        int idx = base + i;
        if (idx < N_NODES) { g_start[idx] = run; run += g_cntd[idx]; }
    }
}

__global__ void scanSR_a_kernel() {
    int idx = blockIdx.x * SCAN_BLK + threadIdx.x;
    int lane = threadIdx.x & 31;
    int wid = threadIdx.x >> 5;
    int flag = (idx < NRN && g_cntSR[idx] > 0) ? 1 : 0;
    unsigned m = __ballot_sync(0xFFFFFFFFu, flag);
    __shared__ int wsum[SCAN_BLK / 32];
    if (lane == 0) wsum[wid] = __popc(m);
    __syncthreads();
    if (threadIdx.x == 0) {
        int s = 0;
        #pragma unroll
        for (int w = 0; w < SCAN_BLK / 32; w++) s += wsum[w];
        g_blkcnt[blockIdx.x] = s;
    }
}

__global__ void scanSR_b_kernel() {
    __shared__ int part[1024];
    int t = threadIdx.x;
    const int CH = (SCAN_GRID + 1023) / 1024;   // 2
    int base = t * CH;
    int s = 0;
    #pragma unroll
    for (int i = 0; i < CH; i++) {
        int idx = base + i;
        if (idx < SCAN_GRID) s += g_blkcnt[idx];
    }
    part[t] = s;
    __syncthreads();
    for (int off = 1; off < 1024; off <<= 1) {
        int v = (t >= off) ? part[t - off] : 0;
        __syncthreads();
        part[t] += v;
        __syncthreads();
    }
    int run = (t > 0) ? part[t - 1] : 0;
    #pragma unroll
    for (int i = 0; i < CH; i++) {
        int idx = base + i;
        if (idx < SCAN_GRID) { g_blkbase[idx] = run; run += g_blkcnt[idx]; }
    }
    if (t == 1023) g_cumRel[N_REL] = part[1023];
}

// rank computation + fused jb (threadfence/last-block pattern)
__global__ void scanSR_c_kernel() {
    int idx = blockIdx.x * SCAN_BLK + threadIdx.x;
    int lane = threadIdx.x & 31;
    int wid = threadIdx.x >> 5;
    int flag = (idx < NRN && g_cntSR[idx] > 0) ? 1 : 0;
    unsigned m = __ballot_sync(0xFFFFFFFFu, flag);
    int wpre = __popc(m & ((1u << lane) - 1));
    __shared__ int wsum[SCAN_BLK / 32];
    if (lane == 0) wsum[wid] = __popc(m);
    __syncthreads();
    int wbase = 0;
    #pragma unroll
    for (int w = 0; w < SCAN_BLK / 32; w++)
        if (w < wid) wbase += wsum[w];
    int rank = g_blkbase[blockIdx.x] + wbase + wpre;
    if (flag) g_jobrank[idx] = rank;
    if (idx < NRN && idx % N_NODES == 0) g_cumRel[idx / N_NODES] = rank;

    __threadfence();
    __syncthreads();
    if (threadIdx.x == 0) {
        int old = atomicAdd(&g_done, 1);
        if (old == gridDim.x - 1) {
            g_jb[0] = 0;
            int b = ROOTPAD;
            for (int r = 0; r < N_REL; r++) {
                g_jb[1 + r] = b;
                int c = g_cumRel[r + 1] - g_cumRel[r];
                b += (c + 127) & ~127;
            }
            g_jb[11] = b;
        }
    }
}

__global__ void jobinit_kernel() {
    int i = blockIdx.x * blockDim.x + threadIdx.x;
    if (i < NJMAX) g_joblist[i] = (i < N_NODES) ? i : 0;
}

__global__ void jobbuild_kernel() {
    int i = blockIdx.x * blockDim.x + threadIdx.x;
    if (i >= NRN) return;
    if (g_cntSR[i] > 0) {
        int r = i / N_NODES, src = i % N_NODES;
        int idx = g_jb[1 + r] + (g_jobrank[i] - g_cumRel[r]);
        g_joblist[idx] = src;
        g_jobidx[i] = idx * 64;        // u32 offset, premultiplied
    }
}

__global__ void fill_kernel(const int* __restrict__ ei, const int* __restrict__ et) {
    int e = blockIdx.x * blockDim.x + threadIdx.x;
    if (e >= N_EDGES) return;
    int src = ei[e];
    int dst = ei[N_EDGES + e];
    int r   = et[e];
    int pos = g_start[dst] + atomicAdd(&g_fill[dst], 1);
    float w = 1.0f / (float)g_cnt[dst * N_REL + r];
    g_epk[pos] = make_int2(g_jobidx[r * N_NODES + src], __float_as_int(w));
}

// pack weights TRANSPOSED as fp16: g_Bwh[l][rr][n][k] = W[k][n]
__global__ void bw_kernel(const float* __restrict__ rel_w, const float* __restrict__ root_w) {
    size_t idx = (size_t)blockIdx.x * blockDim.x + threadIdx.x;
    if (idx >= (size_t)N_LAYERS * 11 * 16384) return;
    int l = idx / (11 * 16384);
    int rem = idx % (11 * 16384);
    int rr = rem / 16384;
    int n = (rem % 16384) / 128, k = rem % 128;
    float v;
    if (rr == 0)
        v = root_w[(size_t)l * 16384 + k * 128 + n];
    else
        v = rel_w[(size_t)l * N_REL * 16384 + (size_t)(rr - 1) * 16384 + k * 128 + n];
    g_Bwh[idx] = __float2half_rn(v);
}

// ---------------- input projection (writes fp32 h and fp16 copy) ----------------
#define BM 64
#define BK 16
__global__ void proj_kernel(const float* __restrict__ x, const float* __restrict__ Wp,
                            const float* __restrict__ bp) {
    __shared__ float As[BK][BM + 4];
    __shared__ float Bs[BK][HIDDEN];
    int tid = threadIdx.x;
    int tm = tid >> 5, tn = tid & 31;
    int row0 = blockIdx.x * BM;
    float acc[8][4];
    #pragma unroll
    for (int i = 0; i < 8; i++)
        #pragma unroll
        for (int j = 0; j < 4; j++) acc[i][j] = 0.f;

    for (int k0 = 0; k0 < IN_DIM; k0 += BK) {
        {
            int r = tid >> 2, kc = (tid & 3) * 4, grow = row0 + r;
            float4 v = make_float4(0.f, 0.f, 0.f, 0.f);
            if (grow < N_NODES) v = *(const float4*)&x[(size_t)grow * IN_DIM + k0 + kc];
            As[kc + 0][r] = v.x; As[kc + 1][r] = v.y; As[kc + 2][r] = v.z; As[kc + 3][r] = v.w;
        }
        #pragma unroll
        for (int i = 0; i < 2; i++) {
            int f = tid + i * 256;
            int kk = f >> 5, c4 = (f & 31) * 4;
            *(float4*)&Bs[kk][c4] = *(const float4*)&Wp[(size_t)(k0 + kk) * HIDDEN + c4];
        }
        __syncthreads();
        #pragma unroll
        for (int kk = 0; kk < BK; kk++) {
            float a[8], b[4];
            *(float4*)&a[0] = *(const float4*)&As[kk][tm * 8];
            *(float4*)&a[4] = *(const float4*)&As[kk][tm * 8 + 4];
            *(float4*)&b[0] = *(const float4*)&Bs[kk][tn * 4];
            #pragma unroll
            for (int i = 0; i < 8; i++)
                #pragma unroll
                for (int j = 0; j < 4; j++) acc[i][j] = fmaf(a[i], b[j], acc[i][j]);
        }
        __syncthreads();
    }
    int n0 = tn * 4;
    float4 bb = *(const float4*)&bp[n0];
    #pragma unroll
    for (int i = 0; i < 8; i++) {
        int grow = row0 + tm * 8 + i;
        if (grow < N_NODES) {
            float4 o = make_float4(acc[i][0] + bb.x, acc[i][1] + bb.y,
                                   acc[i][2] + bb.z, acc[i][3] + bb.w);
            *(float4*)&g_h[0][(size_t)grow * HIDDEN + n0] = o;
            uint2 hv;
            hv.x = pack_h2(o.x, o.y);
            hv.y = pack_h2(o.z, o.w);
            *(uint2*)&g_hh[(size_t)grow * HIDDEN + n0] = hv;
        }
    }
}

// ---------------- compacted fp16 GEMM, software-pipelined chunks ----------------
#define APH 72
#define BPH 72

__global__ void __launch_bounds__(256, 2)
gemmc_kernel(int l) {
    __shared__ __half As[128 * APH];     // [m][k-chunk]
    __shared__ __half Bs[128 * BPH];     // [n][k-chunk]
    __shared__ int rows[128];

    int jobs0 = blockIdx.x * 128;
    if (jobs0 >= g_jb[11]) return;
    int rr = 0;
    #pragma unroll
    for (int r = 1; r < 11; r++)
        if (jobs0 >= g_jb[r]) rr = r;

    int tid = threadIdx.x;
    int wid = tid >> 5;
    int lane = tid & 31;
    int gq = lane >> 2;
    int tq = lane & 3;
    int wm = (wid >> 1) * 32;
    int wn = (wid & 1) * 64;
    const __half* Bw = g_Bwh + ((size_t)l * 11 + rr) * 16384;

    if (tid < 128) rows[tid] = g_joblist[jobs0 + tid];
    __syncthreads();

    float c[2][8][4];
    #pragma unroll
    for (int mi = 0; mi < 2; mi++)
        #pragma unroll
        for (int nj = 0; nj < 8; nj++)
            #pragma unroll
            for (int q = 0; q < 4; q++) c[mi][nj][q] = 0.f;

    // ldmatrix base addresses (bytes); step +32B per k16-step
    uint32_t aAddr[2], bAddr[4];
    {
        uint32_t asBase = smem_u32(As);
        uint32_t bsBase = smem_u32(Bs);
        int arow = wm + (lane & 15);
        int akof = (lane >> 4) * 8;
        #pragma unroll
        for (int mi = 0; mi < 2; mi++)
            aAddr[mi] = asBase + (uint32_t)(((arow + mi * 16) * APH + akof) * 2);
        int bn = ((lane >> 4) << 3) + (lane & 7);
        int bkof = ((lane >> 3) & 1) * 8;
        #pragma unroll
        for (int j = 0; j < 4; j++)
            bAddr[j] = bsBase + (uint32_t)(((wn + 16 * j + bn) * BPH + bkof) * 2);
    }

    int rIdx = tid >> 3, uIdx = tid & 7;   // each thread owns (r, u) slots, 4 apart in r

    // ---- chunk 0: global loads ----
    uint4 av[4], bv[4];
    #pragma unroll
    for (int t = 0; t < 4; t++)
        av[t] = *(const uint4*)&g_hh[(size_t)rows[rIdx + t * 32] * HIDDEN + uIdx * 8];
    #pragma unroll
    for (int t = 0; t < 4; t++)
        bv[t] = *(const uint4*)&Bw[(size_t)(rIdx + t * 32) * 128 + uIdx * 8];

    // ---- store chunk 0 to smem ----
    #pragma unroll
    for (int t = 0; t < 4; t++)
        *(uint4*)&As[(rIdx + t * 32) * APH + uIdx * 8] = av[t];
    #pragma unroll
    for (int t = 0; t < 4; t++)
        *(uint4*)&Bs[(rIdx + t * 32) * BPH + uIdx * 8] = bv[t];

    // ---- prefetch chunk 1 globals (latency hidden behind chunk-0 mma) ----
    uint4 av1[4], bv1[4];
    #pragma unroll
    for (int t = 0; t < 4; t++)
        av1[t] = *(const uint4*)&g_hh[(size_t)rows[rIdx + t * 32] * HIDDEN + 64 + uIdx * 8];
    #pragma unroll
    for (int t = 0; t < 4; t++)
        bv1[t] = *(const uint4*)&Bw[(size_t)(rIdx + t * 32) * 128 + 64 + uIdx * 8];

    __syncthreads();

    // ---- mma chunk 0 ----
    #pragma unroll
    for (int s = 0; s < 4; s++) {
        uint32_t koff = (uint32_t)(s * 32);
        uint32_t a[2][4], b[8][2];
        #pragma unroll
        for (int mi = 0; mi < 2; mi++)
            LDM_X4(a[mi][0], a[mi][1], a[mi][2], a[mi][3], aAddr[mi] + koff);
        #pragma unroll
        for (int j = 0; j < 4; j++)
            LDM_X4(b[2 * j][0], b[2 * j][1], b[2 * j + 1][0], b[2 * j + 1][1],
                   bAddr[j] + koff);
        #pragma unroll
        for (int mi = 0; mi < 2; mi++)
            #pragma unroll
            for (int nj = 0; nj < 8; nj++)
                mma_f16(c[mi][nj], a[mi], b[nj]);
    }
    __syncthreads();

    // ---- store chunk 1 to smem ----
    #pragma unroll
    for (int t = 0; t < 4; t++)
        *(uint4*)&As[(rIdx + t * 32) * APH + uIdx * 8] = av1[t];
    #pragma unroll
    for (int t = 0; t < 4; t++)
        *(uint4*)&Bs[(rIdx + t * 32) * BPH + uIdx * 8] = bv1[t];
    __syncthreads();

    // ---- mma chunk 1 ----
    #pragma unroll
    for (int s = 0; s < 4; s++) {
        uint32_t koff = (uint32_t)(s * 32);
        uint32_t a[2][4], b[8][2];
        #pragma unroll
        for (int mi = 0; mi < 2; mi++)
            LDM_X4(a[mi][0], a[mi][1], a[mi][2], a[mi][3], aAddr[mi] + koff);
        #pragma unroll
        for (int j = 0; j < 4; j++)
            LDM_X4(b[2 * j][0], b[2 * j][1], b[2 * j + 1][0], b[2 * j + 1][1],
                   bAddr[j] + koff);
        #pragma unroll
        for (int mi = 0; mi < 2; mi++)
            #pragma unroll
            for (int nj = 0; nj < 8; nj++)
                mma_f16(c[mi][nj], a[mi], b[nj]);
    }

    // store to compact Y (fp16x2)
    #pragma unroll
    for (int mi = 0; mi < 2; mi++) {
        int j0 = jobs0 + wm + mi * 16 + gq;
        #pragma unroll
        for (int nj = 0; nj < 8; nj++) {
            int cb = wn + nj * 8 + 2 * tq;
            g_Yc[(size_t)j0 * 64 + (cb >> 1)]       = pack_h2(c[mi][nj][0], c[mi][nj][1]);
            g_Yc[(size_t)(j0 + 8) * 64 + (cb >> 1)] = pack_h2(c[mi][nj][2], c[mi][nj][3]);
        }
    }
}

// ---------------- fused CSR gather + bias + LN + ReLU + residual ----------------
__device__ __forceinline__ void fma_h2(float4& acc, uint2 v, float w) {
    float2 a = __half22float2(*(__half2*)&v.x);
    float2 b = __half22float2(*(__half2*)&v.y);
    acc.x = fmaf(a.x, w, acc.x);
    acc.y = fmaf(a.y, w, acc.y);
    acc.z = fmaf(b.x, w, acc.z);
    acc.w = fmaf(b.y, w, acc.w);
}

__global__ void gather_ln_kernel(const float* __restrict__ conv_b, const float* __restrict__ ln_g,
                                 const float* __restrict__ ln_b, int l, int cur) {
    int wid = threadIdx.x >> 5;
    int lane = threadIdx.x & 31;
    int row = blockIdx.x * 8 + wid;
    if (row >= N_NODES) return;
    int n0 = lane * 4;
    int lo2 = lane * 2;
    const float* hcur = g_h[cur];
    float* hnext = g_h[cur ^ 1];

    float4 acc;
    {
        uint2 rv = *(const uint2*)&g_Yc[(size_t)row * 64 + lo2];   // root job = identity
        float2 a = __half22float2(*(__half2*)&rv.x);
        float2 b = __half22float2(*(__half2*)&rv.y);
        float4 cb = *(const float4*)&conv_b[l * HIDDEN + n0];
        acc.x = a.x + cb.x; acc.y = a.y + cb.y; acc.z = b.x + cb.z; acc.w = b.y + cb.w;
    }

    int s = g_start[row];
    int e = s + g_cntd[row];
    int i = s;
    for (; i + 8 <= e; i += 8) {
        int2 p0 = g_epk[i],     p1 = g_epk[i + 1];
        int2 p2 = g_epk[i + 2], p3 = g_epk[i + 3];
        int2 p4 = g_epk[i + 4], p5 = g_epk[i + 5];
        int2 p6 = g_epk[i + 6], p7 = g_epk[i + 7];
        uint2 v0 = *(const uint2*)&g_Yc[(size_t)p0.x + lo2];
        uint2 v1 = *(const uint2*)&g_Yc[(size_t)p1.x + lo2];
        uint2 v2 = *(const uint2*)&g_Yc[(size_t)p2.x + lo2];
        uint2 v3 = *(const uint2*)&g_Yc[(size_t)p3.x + lo2];
        uint2 v4 = *(const uint2*)&g_Yc[(size_t)p4.x + lo2];
        uint2 v5 = *(const uint2*)&g_Yc[(size_t)p5.x + lo2];
        uint2 v6 = *(const uint2*)&g_Yc[(size_t)p6.x + lo2];
        uint2 v7 = *(const uint2*)&g_Yc[(size_t)p7.x + lo2];
        fma_h2(acc, v0, __int_as_float(p0.y));
        fma_h2(acc, v1, __int_as_float(p1.y));
        fma_h2(acc, v2, __int_as_float(p2.y));
        fma_h2(acc, v3, __int_as_float(p3.y));
        fma_h2(acc, v4, __int_as_float(p4.y));
        fma_h2(acc, v5, __int_as_float(p5.y));
        fma_h2(acc, v6, __int_as_float(p6.y));
        fma_h2(acc, v7, __int_as_float(p7.y));
    }
    for (; i < e; i++) {
        int2 p = g_epk[i];
        uint2 v = *(const uint2*)&g_Yc[(size_t)p.x + lo2];
        fma_h2(acc, v, __int_as_float(p.y));
    }

    float sm = acc.x + acc.y + acc.z + acc.w;
    float q = acc.x * acc.x + acc.y * acc.y + acc.z * acc.z + acc.w * acc.w;
    #pragma unroll
    for (int o = 16; o > 0; o >>= 1) {
        sm += __shfl_xor_sync(0xFFFFFFFFu, sm, o);
        q  += __shfl_xor_sync(0xFFFFFFFFu, q, o);
    }
    float mu = sm * (1.0f / HIDDEN);
    float var = q * (1.0f / HIDDEN) - mu * mu;
    float rs = rsqrtf(var + LN_EPS);
    float4 g4 = *(const float4*)&ln_g[l * HIDDEN + n0];
    float4 b4 = *(const float4*)&ln_b[l * HIDDEN + n0];
    float4 rv = *(const float4*)&hcur[(size_t)row * HIDDEN + n0];
    float4 o;
    o.x = fmaxf((acc.x - mu) * rs * g4.x + b4.x, 0.f) + rv.x;
    o.y = fmaxf((acc.y - mu) * rs * g4.y + b4.y, 0.f) + rv.y;
    o.z = fmaxf((acc.z - mu) * rs * g4.z + b4.z, 0.f) + rv.z;
    o.w = fmaxf((acc.w - mu) * rs * g4.w + b4.w, 0.f) + rv.w;
    *(float4*)&hnext[(size_t)row * HIDDEN + n0] = o;
    uint2 hv;
    hv.x = pack_h2(o.x, o.y);
    hv.y = pack_h2(o.z, o.w);
    *(uint2*)&g_hh[(size_t)row * HIDDEN + n0] = hv;
}

// ---------------- pooling ----------------
__device__ __forceinline__ int lower_bound_dev(const int* __restrict__ a, int n, int v) {
    int lo = 0, hi = n;
    while (lo < hi) { int mid = (lo + hi) >> 1; if (a[mid] < v) lo = mid + 1; else hi = mid; }
    return lo;
}

__global__ void pool_kernel(const int* __restrict__ batch, float* __restrict__ out, int finalbuf) {
    int g = blockIdx.x;
    int tid = threadIdx.x;
    int start = lower_bound_dev(batch, N_NODES, g);
    int end   = lower_bound_dev(batch, N_NODES, g + 1);
    const float* h = g_h[finalbuf];
    float acc = 0.f;
    for (int i = start; i < end; i++)
        acc += h[(size_t)i * HIDDEN + tid];
    out[g * HIDDEN + tid] = acc;
}

// ---------------- launch ----------------
extern "C" void kernel_launch(void* const* d_in, const int* in_sizes, int n_in,
                              void* d_out, int out_size) {
    const float* x      = (const float*)d_in[0];
    const int* ei       = (const int*)d_in[1];
    const int* et       = (const int*)d_in[2];
    const int* batch    = (const int*)d_in[3];
    const float* Wp     = (const float*)d_in[4];
    const float* bp     = (const float*)d_in[5];
    const float* rel_w  = (const float*)d_in[6];
    const float* root_w = (const float*)d_in[7];
    const float* conv_b = (const float*)d_in[8];
    const float* ln_g   = (const float*)d_in[9];
    const float* ln_b   = (const float*)d_in[10];
    float* out = (float*)d_out;

    // structure setup
    init_kernel<<<(NRN + 255) / 256, 256>>>();
    count_kernel<<<(N_EDGES + 255) / 256, 256>>>(ei, et);
    scan_dst_kernel<<<1, 1024>>>();
    scanSR_a_kernel<<<SCAN_GRID, SCAN_BLK>>>();
    scanSR_b_kernel<<<1, 1024>>>();
    scanSR_c_kernel<<<SCAN_GRID, SCAN_BLK>>>();   // jb fused (last block)
    jobinit_kernel<<<(NJMAX + 255) / 256, 256>>>();
    jobbuild_kernel<<<(NRN + 255) / 256, 256>>>();
    fill_kernel<<<(N_EDGES + 255) / 256, 256>>>(ei, et);

    // weights packed once for all layers (fp16, transposed)
    bw_kernel<<<(int)(((size_t)N_LAYERS * 11 * 16384 + 255) / 256), 256>>>(rel_w, root_w);

    proj_kernel<<<(N_NODES + BM - 1) / BM, 256>>>(x, Wp, bp);

    for (int l = 0; l < N_LAYERS; l++) {
        int cur = l & 1;
        gemmc_kernel<<<MAXTILES, 256>>>(l);
        gather_ln_kernel<<<(N_NODES + 7) / 8, 256>>>(conv_b, ln_g, ln_b, l, cur);
    }

    pool_kernel<<<N_GRAPHS, HIDDEN>>>(batch, out, 0);
}